// round 6
// baseline (speedup 1.0000x reference)
#include <cuda_runtime.h>
#include <cstdint>

#define NROWS 262144
#define FEAT 64
#define DD 128
#define WARPS 16
#define RPW 8
#define ROWS_PER_BLOCK (WARPS * RPW)   // 128

typedef unsigned long long u64t;

// Scratch: double-buffered node state (padding row dropped — never gathered,
// never part of the output).
__device__ float g_x0[(size_t)NROWS * DD];
__device__ float g_x1[(size_t)NROWS * DD];

__device__ __forceinline__ float lk(float x) { return x >= 0.f ? x : 0.01f * x; }

__device__ __forceinline__ u64t pk2(float lo, float hi) {
    u64t r; asm("mov.b64 %0, {%1, %2};" : "=l"(r) : "f"(lo), "f"(hi)); return r;
}
__device__ __forceinline__ u64t dup2(float v) { return pk2(v, v); }
__device__ __forceinline__ void fma2(u64t& d, u64t a, u64t b) {
    asm("fma.rn.f32x2 %0, %1, %2, %0;" : "+l"(d) : "l"(a), "l"(b));
}
__device__ __forceinline__ float2 unpk(u64t v) {
    float2 f; asm("mov.b64 {%0, %1}, %2;" : "=f"(f.x), "=f"(f.y) : "l"(v)); return f;
}

// ---------------------------------------------------------------------------
// Kernel A: normalize -> embed GEMM(64->128)+leaky -> layer GEMM(128->128)
//           double-leaky + residual -> layernorm * 0.5  -> g_x0
// Weights live in SMEM (crossbar), activations staged per-warp (broadcast LDS).
// ---------------------------------------------------------------------------
__global__ __launch_bounds__(512, 1)
void kernelA(const float* __restrict__ raw,
             const float* __restrict__ smean,
             const float* __restrict__ sstd,
             const float* __restrict__ W1,
             const float* __restrict__ b1,
             const float* __restrict__ W2,
             const float* __restrict__ b2)
{
    extern __shared__ float sm[];
    float* sW1 = sm;                          // 64*128   (32 KB)
    float* sW2 = sW1 + FEAT * DD;             // 128*128  (64 KB)
    float* sB1 = sW2 + DD * DD;               // 128
    float* sB2 = sB1 + DD;                    // 128
    float* sX  = sB2 + DD;                    // WARPS*RPW*FEAT (32 KB)
    float* sH  = sX + WARPS * RPW * FEAT;     // WARPS*RPW*DD   (64 KB)

    const int tid  = threadIdx.x;
    const int warp = tid >> 5, lane = tid & 31;
    const int row0 = blockIdx.x * ROWS_PER_BLOCK + warp * RPW;
    float* xs = sX + warp * (RPW * FEAT);
    float* hs = sH + warp * (RPW * DD);

    // stage weights + biases into smem
    for (int i = tid; i < (FEAT * DD) / 4; i += 512)
        reinterpret_cast<float4*>(sW1)[i] = __ldg(&reinterpret_cast<const float4*>(W1)[i]);
    for (int i = tid; i < (DD * DD) / 4; i += 512)
        reinterpret_cast<float4*>(sW2)[i] = __ldg(&reinterpret_cast<const float4*>(W2)[i]);
    if (tid < DD) { sB1[tid] = b1[tid]; sB2[tid] = b2[tid]; }

    // stage normalized inputs (row-major; reads in GEMM1 are warp-broadcasts)
    float2 m2 = reinterpret_cast<const float2*>(smean)[lane];
    float2 s2 = reinterpret_cast<const float2*>(sstd)[lane];
    const float inx = 1.f / (s2.x + 0.001f), iny = 1.f / (s2.y + 0.001f);
    #pragma unroll
    for (int r = 0; r < RPW; r++) {
        float2 v = reinterpret_cast<const float2*>(raw + (size_t)(row0 + r) * FEAT)[lane];
        v.x = (v.x - m2.x) * inx;
        v.y = (v.y - m2.y) * iny;
        reinterpret_cast<float2*>(xs + r * FEAT)[lane] = v;
    }
    __syncthreads();

    u64t acc[RPW][2];
    // ---- GEMM1: h = leaky(x @ W1 + b1) ----
    {
        float4 bb = reinterpret_cast<float4*>(sB1)[lane];
        u64t blo = pk2(bb.x, bb.y), bhi = pk2(bb.z, bb.w);
        #pragma unroll
        for (int r = 0; r < RPW; r++) { acc[r][0] = blo; acc[r][1] = bhi; }
    }
    #pragma unroll
    for (int k4 = 0; k4 < FEAT; k4 += 4) {
        float4 xr[RPW];
        #pragma unroll
        for (int r = 0; r < RPW; r++)
            xr[r] = *reinterpret_cast<float4*>(xs + r * FEAT + k4);   // broadcast LDS.128
        #pragma unroll
        for (int kk = 0; kk < 4; kk++) {
            ulonglong2 w = *reinterpret_cast<ulonglong2*>(sW1 + (k4 + kk) * DD + lane * 4);
            #pragma unroll
            for (int r = 0; r < RPW; r++) {
                float xv = (kk == 0) ? xr[r].x : (kk == 1) ? xr[r].y
                         : (kk == 2) ? xr[r].z : xr[r].w;
                u64t xd = dup2(xv);
                fma2(acc[r][0], xd, w.x);
                fma2(acc[r][1], xd, w.y);
            }
        }
    }
    #pragma unroll
    for (int r = 0; r < RPW; r++) {
        float2 a0 = unpk(acc[r][0]), a1 = unpk(acc[r][1]);
        float4 h = make_float4(lk(a0.x), lk(a0.y), lk(a1.x), lk(a1.y));
        reinterpret_cast<float4*>(hs + r * DD)[lane] = h;
    }
    __syncwarp();

    // ---- GEMM2: y = leaky(leaky(h @ W2 + b2)) + h ----
    {
        float4 bb = reinterpret_cast<float4*>(sB2)[lane];
        u64t blo = pk2(bb.x, bb.y), bhi = pk2(bb.z, bb.w);
        #pragma unroll
        for (int r = 0; r < RPW; r++) { acc[r][0] = blo; acc[r][1] = bhi; }
    }
    #pragma unroll 8
    for (int k4 = 0; k4 < DD; k4 += 4) {
        float4 xr[RPW];
        #pragma unroll
        for (int r = 0; r < RPW; r++)
            xr[r] = *reinterpret_cast<float4*>(hs + r * DD + k4);
        #pragma unroll
        for (int kk = 0; kk < 4; kk++) {
            ulonglong2 w = *reinterpret_cast<ulonglong2*>(sW2 + (k4 + kk) * DD + lane * 4);
            #pragma unroll
            for (int r = 0; r < RPW; r++) {
                float hv = (kk == 0) ? xr[r].x : (kk == 1) ? xr[r].y
                         : (kk == 2) ? xr[r].z : xr[r].w;
                u64t hd = dup2(hv);
                fma2(acc[r][0], hd, w.x);
                fma2(acc[r][1], hd, w.y);
            }
        }
    }

    // ---- layernorm * 0.5 ----
    const float invD = 1.0f / DD;
    #pragma unroll
    for (int r = 0; r < RPW; r++) {
        float4 h = reinterpret_cast<float4*>(hs + r * DD)[lane];
        float2 a0 = unpk(acc[r][0]), a1 = unpk(acc[r][1]);
        float y0 = lk(lk(a0.x)) + h.x;
        float y1 = lk(lk(a0.y)) + h.y;
        float y2 = lk(lk(a1.x)) + h.z;
        float y3 = lk(lk(a1.y)) + h.w;
        float s = y0 + y1 + y2 + y3;
        float q = y0 * y0 + y1 * y1 + y2 * y2 + y3 * y3;
        #pragma unroll
        for (int off = 16; off > 0; off >>= 1) {
            s += __shfl_xor_sync(0xffffffffu, s, off);
            q += __shfl_xor_sync(0xffffffffu, q, off);
        }
        float mu  = s * invD;
        float var = q * invD - mu * mu;
        float sc  = rsqrtf(var + 1e-5f) * 0.5f;
        float4 o  = make_float4((y0 - mu) * sc, (y1 - mu) * sc,
                                (y2 - mu) * sc, (y3 - mu) * sc);
        reinterpret_cast<float4*>(g_x0 + (size_t)(row0 + r) * DD)[lane] = o;
    }
}

// ---------------------------------------------------------------------------
// Kernel B: one DEPTH step. gather-mean -> node GEMM + leaky -> rezero residual.
// PHASE 0: g_x0 -> g_x1.  PHASE 1: g_x1 -> d_out, fused with w/v GEMVs.
// ---------------------------------------------------------------------------
template<int PHASE>
__global__ __launch_bounds__(512, 1)
void kernelB(const int* __restrict__ idmap,
             const float* __restrict__ Wn,
             const float* __restrict__ bn,
             const float* __restrict__ rez,
             const float* __restrict__ Ww,
             const float* __restrict__ Wv,
             float* __restrict__ outx,
             float* __restrict__ outw,
             float* __restrict__ outv)
{
    extern __shared__ float sm[];
    float* sW = sm;                 // 128*128 (64 KB)
    float* sB = sW + DD * DD;       // 128
    float* sG = sB + DD;            // WARPS*RPW*DD (64 KB)

    const int tid  = threadIdx.x;
    const int warp = tid >> 5, lane = tid & 31;
    const int row0 = blockIdx.x * ROWS_PER_BLOCK + warp * RPW;
    float* gs = sG + warp * (RPW * DD);

    for (int i = tid; i < (DD * DD) / 4; i += 512)
        reinterpret_cast<float4*>(sW)[i] = __ldg(&reinterpret_cast<const float4*>(Wn)[i]);
    if (tid < DD) sB[tid] = bn[tid];

    const float scale = 0.25f * __ldg(rez);   // SCALE_STEPS * rezero
    const float* __restrict__ xin = (PHASE == 0) ? g_x0 : g_x1;

    // gather-mean into shared (row-major; reads below are warp-broadcasts)
    #pragma unroll
    for (int r = 0; r < RPW; r++) {
        int2 pr = reinterpret_cast<const int2*>(idmap)[row0 + r];
        float4 va = reinterpret_cast<const float4*>(xin + (size_t)pr.x * DD)[lane];
        float4 vb = reinterpret_cast<const float4*>(xin + (size_t)pr.y * DD)[lane];
        float4 g  = make_float4(0.5f * (va.x + vb.x), 0.5f * (va.y + vb.y),
                                0.5f * (va.z + vb.z), 0.5f * (va.w + vb.w));
        reinterpret_cast<float4*>(gs + r * DD)[lane] = g;
    }
    __syncthreads();

    u64t acc[RPW][2];
    {
        float4 bb = reinterpret_cast<float4*>(sB)[lane];
        u64t blo = pk2(bb.x, bb.y), bhi = pk2(bb.z, bb.w);
        #pragma unroll
        for (int r = 0; r < RPW; r++) { acc[r][0] = blo; acc[r][1] = bhi; }
    }
    #pragma unroll 8
    for (int k4 = 0; k4 < DD; k4 += 4) {
        float4 xr[RPW];
        #pragma unroll
        for (int r = 0; r < RPW; r++)
            xr[r] = *reinterpret_cast<float4*>(gs + r * DD + k4);
        #pragma unroll
        for (int kk = 0; kk < 4; kk++) {
            ulonglong2 w = *reinterpret_cast<ulonglong2*>(sW + (k4 + kk) * DD + lane * 4);
            #pragma unroll
            for (int r = 0; r < RPW; r++) {
                float gv = (kk == 0) ? xr[r].x : (kk == 1) ? xr[r].y
                         : (kk == 2) ? xr[r].z : xr[r].w;
                u64t gd = dup2(gv);
                fma2(acc[r][0], gd, w.x);
                fma2(acc[r][1], gd, w.y);
            }
        }
    }

    float4 ww, vv;
    if (PHASE == 1) {
        ww = __ldg(&reinterpret_cast<const float4*>(Ww)[lane]);
        vv = __ldg(&reinterpret_cast<const float4*>(Wv)[lane]);
    }

    #pragma unroll
    for (int r = 0; r < RPW; r++) {
        const int row = row0 + r;
        float4 xi = reinterpret_cast<const float4*>(xin + (size_t)row * DD)[lane];
        float2 a0 = unpk(acc[r][0]), a1 = unpk(acc[r][1]);
        float4 o;
        o.x = xi.x + lk(a0.x) * scale;
        o.y = xi.y + lk(a0.y) * scale;
        o.z = xi.z + lk(a1.x) * scale;
        o.w = xi.w + lk(a1.y) * scale;
        if (PHASE == 0) {
            reinterpret_cast<float4*>(g_x1 + (size_t)row * DD)[lane] = o;
        } else {
            reinterpret_cast<float4*>(outx + (size_t)row * DD)[lane] = o;
            float pw = o.x * ww.x + o.y * ww.y + o.z * ww.z + o.w * ww.w;
            float pv = o.x * vv.x + o.y * vv.y + o.z * vv.z + o.w * vv.w;
            #pragma unroll
            for (int off = 16; off > 0; off >>= 1) {
                pw += __shfl_xor_sync(0xffffffffu, pw, off);
                pv += __shfl_xor_sync(0xffffffffu, pv, off);
            }
            if (lane == 0) { outw[row] = pw; outv[row] = pv; }
        }
    }
}

extern "C" void kernel_launch(void* const* d_in, const int* in_sizes, int n_in,
                              void* d_out, int out_size)
{
    const float* raw   = (const float*)d_in[0];
    // d_in[1] = uids (unused)
    const int*   idmap = (const int*)  d_in[2];
    const float* smean = (const float*)d_in[3];
    const float* sstd  = (const float*)d_in[4];
    const float* W1    = (const float*)d_in[5];
    const float* b1    = (const float*)d_in[6];
    const float* W2    = (const float*)d_in[7];
    const float* b2    = (const float*)d_in[8];
    const float* Wn    = (const float*)d_in[9];
    const float* bn    = (const float*)d_in[10];
    const float* rez   = (const float*)d_in[11];
    const float* Ww    = (const float*)d_in[12];
    const float* Wv    = (const float*)d_in[13];
    float* out = (float*)d_out;

    const int smemA = (FEAT * DD + DD * DD + 2 * DD +
                       WARPS * RPW * FEAT + WARPS * RPW * DD) * 4;   // ~193 KB
    const int smemB = (DD * DD + DD + WARPS * RPW * DD) * 4;         // ~128.5 KB

    cudaFuncSetAttribute(kernelA,    cudaFuncAttributeMaxDynamicSharedMemorySize, smemA);
    cudaFuncSetAttribute(kernelB<0>, cudaFuncAttributeMaxDynamicSharedMemorySize, smemB);
    cudaFuncSetAttribute(kernelB<1>, cudaFuncAttributeMaxDynamicSharedMemorySize, smemB);

    dim3 grid(NROWS / ROWS_PER_BLOCK);   // 2048
    kernelA<<<grid, 512, smemA>>>(raw, smean, sstd, W1, b1, W2, b2);
    kernelB<0><<<grid, 512, smemB>>>(idmap, Wn, bn, rez, Ww, Wv,
                                     nullptr, nullptr, nullptr);
    kernelB<1><<<grid, 512, smemB>>>(idmap, Wn, bn, rez, Ww, Wv,
                                     out,
                                     out + (size_t)NROWS * DD,
                                     out + (size_t)NROWS * DD + NROWS);
}

// round 7
// speedup vs baseline: 1.0363x; 1.0363x over previous
#include <cuda_runtime.h>
#include <cstdint>

#define NROWS 262144
#define FEAT 64
#define DD 128
#define WARPS 8
#define RPW 8
#define ROWS_PER_BLOCK (WARPS * RPW)   // 64

typedef unsigned long long u64t;

// Scratch: double-buffered node state (padding row dropped — never gathered,
// never part of the output).
__device__ float g_x0[(size_t)NROWS * DD];
__device__ float g_x1[(size_t)NROWS * DD];

// k-pair-interleaved weight images: Wp[p][c] = pack(W[2p][c], W[2p+1][c]).
// W1p additionally has input normalization folded in; g_b1f is the folded bias.
__device__ u64t  g_W1p[(FEAT / 2) * DD];
__device__ u64t  g_W2p[(DD / 2) * DD];
__device__ u64t  g_Wnp[(DD / 2) * DD];
__device__ float g_b1f[DD];

__device__ __forceinline__ float lk(float x) { return x >= 0.f ? x : 0.01f * x; }

__device__ __forceinline__ u64t pk2(float lo, float hi) {
    u64t r; asm("mov.b64 %0, {%1, %2};" : "=l"(r) : "f"(lo), "f"(hi)); return r;
}
__device__ __forceinline__ void fma2(u64t& d, u64t a, u64t b) {
    asm("fma.rn.f32x2 %0, %1, %2, %0;" : "+l"(d) : "l"(a), "l"(b));
}
// horizontal reduce of a k-packed accumulator
__device__ __forceinline__ float red(u64t v) {
    float2 f; asm("mov.b64 {%0, %1}, %2;" : "=f"(f.x), "=f"(f.y) : "l"(v));
    return f.x + f.y;
}

// ---------------------------------------------------------------------------
// Prep: build k-pair weight images; fold normalization into W1/b1.
// grid 3 x 128 threads; thread = output column c.
// ---------------------------------------------------------------------------
__global__ void prep(const float* __restrict__ smean, const float* __restrict__ sstd,
                     const float* __restrict__ W1, const float* __restrict__ b1,
                     const float* __restrict__ W2, const float* __restrict__ Wn)
{
    const int c = threadIdx.x;
    if (blockIdx.x == 0) {
        float bacc = b1[c];
        for (int p = 0; p < FEAT / 2; p++) {
            int k0 = 2 * p, k1 = 2 * p + 1;
            float w0 = W1[k0 * DD + c] / (sstd[k0] + 0.001f);
            float w1 = W1[k1 * DD + c] / (sstd[k1] + 0.001f);
            bacc -= smean[k0] * w0 + smean[k1] * w1;
            g_W1p[p * DD + c] = pk2(w0, w1);
        }
        g_b1f[c] = bacc;
    } else {
        const float* W = (blockIdx.x == 1) ? W2 : Wn;
        u64t* img      = (blockIdx.x == 1) ? g_W2p : g_Wnp;
        for (int p = 0; p < DD / 2; p++)
            img[p * DD + c] = pk2(W[2 * p * DD + c], W[(2 * p + 1) * DD + c]);
    }
}

// one GEMM k4-step: acts xp (2 k-pairs), weight image row pointer, 4-col accs
__device__ __forceinline__ void gstep(u64t acc[4], ulonglong2 xp,
                                      const u64t* __restrict__ Wp, int p, int lane)
{
    #pragma unroll
    for (int pp = 0; pp < 2; pp++) {
        ulonglong2 wlo = __ldg(reinterpret_cast<const ulonglong2*>(Wp + (p + pp) * DD + 2 * lane));
        ulonglong2 whi = __ldg(reinterpret_cast<const ulonglong2*>(Wp + (p + pp) * DD + 64 + 2 * lane));
        u64t a = pp ? xp.y : xp.x;
        fma2(acc[0], a, wlo.x);
        fma2(acc[1], a, wlo.y);
        fma2(acc[2], a, whi.x);
        fma2(acc[3], a, whi.y);
    }
}

// ---------------------------------------------------------------------------
// Kernel A: raw -> embed GEMM(64->128)+leaky -> layer GEMM(128->128)
//           double-leaky + residual -> layernorm * 0.5  -> g_x0
// Normalization is folded into g_W1p/g_b1f. Col ownership per lane:
// {2l, 2l+1, 64+2l, 64+2l+1}.
// ---------------------------------------------------------------------------
__global__ __launch_bounds__(256, 2)
void kernelA(const float* __restrict__ raw, const float* __restrict__ b2)
{
    extern __shared__ float sm[];
    float* sX = sm;                          // WARPS*RPW*FEAT
    float* sH = sX + WARPS * RPW * FEAT;     // WARPS*RPW*DD

    const int tid  = threadIdx.x;
    const int warp = tid >> 5, lane = tid & 31;
    const int row0 = blockIdx.x * ROWS_PER_BLOCK + warp * RPW;
    float* xs = sX + warp * (RPW * FEAT);
    float* hs = sH + warp * (RPW * DD);

    // stage raw rows (row-major; GEMM1 reads are warp-broadcast LDS.128)
    #pragma unroll
    for (int r = 0; r < RPW; r++)
        reinterpret_cast<float2*>(xs + r * FEAT)[lane] =
            reinterpret_cast<const float2*>(raw)[(size_t)(row0 + r) * 32 + lane];
    __syncwarp();

    u64t acc[RPW][4];
    // ---- GEMM1: h = leaky(raw @ W1' + b1') ----
    {
        float2 blo = __ldg(reinterpret_cast<const float2*>(g_b1f + 2 * lane));
        float2 bhi = __ldg(reinterpret_cast<const float2*>(g_b1f + 64 + 2 * lane));
        u64t i0 = pk2(blo.x, 0.f), i1 = pk2(blo.y, 0.f);
        u64t i2 = pk2(bhi.x, 0.f), i3 = pk2(bhi.y, 0.f);
        #pragma unroll
        for (int r = 0; r < RPW; r++) {
            acc[r][0] = i0; acc[r][1] = i1; acc[r][2] = i2; acc[r][3] = i3;
        }
    }
    #pragma unroll
    for (int k4 = 0; k4 < FEAT; k4 += 4) {
        ulonglong2 xp[RPW];
        #pragma unroll
        for (int r = 0; r < RPW; r++)
            xp[r] = *reinterpret_cast<ulonglong2*>(xs + r * FEAT + k4);
        #pragma unroll
        for (int r = 0; r < RPW; r++)
            gstep(acc[r], xp[r], g_W1p, k4 >> 1, lane);
    }
    #pragma unroll
    for (int r = 0; r < RPW; r++) {
        float2 hlo = make_float2(lk(red(acc[r][0])), lk(red(acc[r][1])));
        float2 hhi = make_float2(lk(red(acc[r][2])), lk(red(acc[r][3])));
        *reinterpret_cast<float2*>(hs + r * DD + 2 * lane)      = hlo;
        *reinterpret_cast<float2*>(hs + r * DD + 64 + 2 * lane) = hhi;
    }
    __syncwarp();

    // ---- GEMM2: y = leaky(leaky(h @ W2 + b2)) + h ----
    {
        float2 blo = __ldg(reinterpret_cast<const float2*>(b2 + 2 * lane));
        float2 bhi = __ldg(reinterpret_cast<const float2*>(b2 + 64 + 2 * lane));
        u64t i0 = pk2(blo.x, 0.f), i1 = pk2(blo.y, 0.f);
        u64t i2 = pk2(bhi.x, 0.f), i3 = pk2(bhi.y, 0.f);
        #pragma unroll
        for (int r = 0; r < RPW; r++) {
            acc[r][0] = i0; acc[r][1] = i1; acc[r][2] = i2; acc[r][3] = i3;
        }
    }
    #pragma unroll 8
    for (int k4 = 0; k4 < DD; k4 += 4) {
        ulonglong2 xp[RPW];
        #pragma unroll
        for (int r = 0; r < RPW; r++)
            xp[r] = *reinterpret_cast<ulonglong2*>(hs + r * DD + k4);
        #pragma unroll
        for (int r = 0; r < RPW; r++)
            gstep(acc[r], xp[r], g_W2p, k4 >> 1, lane);
    }

    // ---- layernorm * 0.5 ----
    const float invD = 1.0f / DD;
    #pragma unroll
    for (int r = 0; r < RPW; r++) {
        float2 hlo = *reinterpret_cast<float2*>(hs + r * DD + 2 * lane);
        float2 hhi = *reinterpret_cast<float2*>(hs + r * DD + 64 + 2 * lane);
        float y0 = lk(lk(red(acc[r][0]))) + hlo.x;
        float y1 = lk(lk(red(acc[r][1]))) + hlo.y;
        float y2 = lk(lk(red(acc[r][2]))) + hhi.x;
        float y3 = lk(lk(red(acc[r][3]))) + hhi.y;
        float s = y0 + y1 + y2 + y3;
        float q = y0 * y0 + y1 * y1 + y2 * y2 + y3 * y3;
        #pragma unroll
        for (int off = 16; off > 0; off >>= 1) {
            s += __shfl_xor_sync(0xffffffffu, s, off);
            q += __shfl_xor_sync(0xffffffffu, q, off);
        }
        float mu  = s * invD;
        float var = q * invD - mu * mu;
        float sc  = rsqrtf(var + 1e-5f) * 0.5f;
        float* dst = g_x0 + (size_t)(row0 + r) * DD;
        *reinterpret_cast<float2*>(dst + 2 * lane)      = make_float2((y0 - mu) * sc, (y1 - mu) * sc);
        *reinterpret_cast<float2*>(dst + 64 + 2 * lane) = make_float2((y2 - mu) * sc, (y3 - mu) * sc);
    }
}

// ---------------------------------------------------------------------------
// Kernel B: one DEPTH step. gather-mean -> node GEMM + leaky -> rezero residual.
// PHASE 0: g_x0 -> g_x1.  PHASE 1: g_x1 -> d_out, fused with w/v GEMVs.
// ---------------------------------------------------------------------------
template<int PHASE>
__global__ __launch_bounds__(256, 2)
void kernelB(const int* __restrict__ idmap,
             const float* __restrict__ bn,
             const float* __restrict__ rez,
             const float* __restrict__ Ww,
             const float* __restrict__ Wv,
             float* __restrict__ outx,
             float* __restrict__ outw,
             float* __restrict__ outv)
{
    extern __shared__ float sm[];
    float* sG = sm;                 // WARPS*RPW*DD

    const int tid  = threadIdx.x;
    const int warp = tid >> 5, lane = tid & 31;
    const int row0 = blockIdx.x * ROWS_PER_BLOCK + warp * RPW;
    float* gs = sG + warp * (RPW * DD);

    const float scale = 0.25f * __ldg(rez);   // SCALE_STEPS * rezero
    const float* __restrict__ xin = (PHASE == 0) ? g_x0 : g_x1;

    // gather-mean into shared (row-major)
    #pragma unroll
    for (int r = 0; r < RPW; r++) {
        int2 pr = reinterpret_cast<const int2*>(idmap)[row0 + r];
        float4 va = reinterpret_cast<const float4*>(xin + (size_t)pr.x * DD)[lane];
        float4 vb = reinterpret_cast<const float4*>(xin + (size_t)pr.y * DD)[lane];
        float4 g  = make_float4(0.5f * (va.x + vb.x), 0.5f * (va.y + vb.y),
                                0.5f * (va.z + vb.z), 0.5f * (va.w + vb.w));
        reinterpret_cast<float4*>(gs + r * DD)[lane] = g;
    }
    __syncwarp();

    u64t acc[RPW][4];
    {
        float2 blo = __ldg(reinterpret_cast<const float2*>(bn + 2 * lane));
        float2 bhi = __ldg(reinterpret_cast<const float2*>(bn + 64 + 2 * lane));
        u64t i0 = pk2(blo.x, 0.f), i1 = pk2(blo.y, 0.f);
        u64t i2 = pk2(bhi.x, 0.f), i3 = pk2(bhi.y, 0.f);
        #pragma unroll
        for (int r = 0; r < RPW; r++) {
            acc[r][0] = i0; acc[r][1] = i1; acc[r][2] = i2; acc[r][3] = i3;
        }
    }
    #pragma unroll 8
    for (int k4 = 0; k4 < DD; k4 += 4) {
        ulonglong2 xp[RPW];
        #pragma unroll
        for (int r = 0; r < RPW; r++)
            xp[r] = *reinterpret_cast<ulonglong2*>(gs + r * DD + k4);
        #pragma unroll
        for (int r = 0; r < RPW; r++)
            gstep(acc[r], xp[r], g_Wnp, k4 >> 1, lane);
    }

    float2 wlo, whi, vlo, vhi;
    if (PHASE == 1) {
        wlo = __ldg(reinterpret_cast<const float2*>(Ww + 2 * lane));
        whi = __ldg(reinterpret_cast<const float2*>(Ww + 64 + 2 * lane));
        vlo = __ldg(reinterpret_cast<const float2*>(Wv + 2 * lane));
        vhi = __ldg(reinterpret_cast<const float2*>(Wv + 64 + 2 * lane));
    }

    #pragma unroll
    for (int r = 0; r < RPW; r++) {
        const int row = row0 + r;
        const float* src = xin + (size_t)row * DD;
        float2 xlo = *reinterpret_cast<const float2*>(src + 2 * lane);
        float2 xhi = *reinterpret_cast<const float2*>(src + 64 + 2 * lane);
        float o0 = xlo.x + lk(red(acc[r][0])) * scale;
        float o1 = xlo.y + lk(red(acc[r][1])) * scale;
        float o2 = xhi.x + lk(red(acc[r][2])) * scale;
        float o3 = xhi.y + lk(red(acc[r][3])) * scale;
        float* dst = ((PHASE == 0) ? g_x1 : outx) + (size_t)row * DD;
        *reinterpret_cast<float2*>(dst + 2 * lane)      = make_float2(o0, o1);
        *reinterpret_cast<float2*>(dst + 64 + 2 * lane) = make_float2(o2, o3);
        if (PHASE == 1) {
            float pw = o0 * wlo.x + o1 * wlo.y + o2 * whi.x + o3 * whi.y;
            float pv = o0 * vlo.x + o1 * vlo.y + o2 * vhi.x + o3 * vhi.y;
            #pragma unroll
            for (int off = 16; off > 0; off >>= 1) {
                pw += __shfl_xor_sync(0xffffffffu, pw, off);
                pv += __shfl_xor_sync(0xffffffffu, pv, off);
            }
            if (lane == 0) { outw[row] = pw; outv[row] = pv; }
        }
    }
}

extern "C" void kernel_launch(void* const* d_in, const int* in_sizes, int n_in,
                              void* d_out, int out_size)
{
    const float* raw   = (const float*)d_in[0];
    // d_in[1] = uids (unused)
    const int*   idmap = (const int*)  d_in[2];
    const float* smean = (const float*)d_in[3];
    const float* sstd  = (const float*)d_in[4];
    const float* W1    = (const float*)d_in[5];
    const float* b1    = (const float*)d_in[6];
    const float* W2    = (const float*)d_in[7];
    const float* b2    = (const float*)d_in[8];
    const float* Wn    = (const float*)d_in[9];
    const float* bn    = (const float*)d_in[10];
    const float* rez   = (const float*)d_in[11];
    const float* Ww    = (const float*)d_in[12];
    const float* Wv    = (const float*)d_in[13];
    float* out = (float*)d_out;

    const int smemA = (WARPS * RPW * FEAT + WARPS * RPW * DD) * 4;   // 48 KB
    const int smemB = (WARPS * RPW * DD) * 4;                        // 32 KB

    cudaFuncSetAttribute(kernelA,    cudaFuncAttributeMaxDynamicSharedMemorySize, smemA);
    cudaFuncSetAttribute(kernelB<0>, cudaFuncAttributeMaxDynamicSharedMemorySize, smemB);
    cudaFuncSetAttribute(kernelB<1>, cudaFuncAttributeMaxDynamicSharedMemorySize, smemB);

    dim3 grid(NROWS / ROWS_PER_BLOCK);   // 4096
    prep<<<3, 128>>>(smean, sstd, W1, b1, W2, Wn);
    kernelA<<<grid, 256, smemA>>>(raw, b2);
    kernelB<0><<<grid, 256, smemB>>>(idmap, bn, rez, Ww, Wv,
                                     nullptr, nullptr, nullptr);
    kernelB<1><<<grid, 256, smemB>>>(idmap, bn, rez, Ww, Wv,
                                     out,
                                     out + (size_t)NROWS * DD,
                                     out + (size_t)NROWS * DD + NROWS);
}

// round 8
// speedup vs baseline: 1.3022x; 1.2565x over previous
#include <cuda_runtime.h>
#include <cuda_fp16.h>
#include <cstdint>

#define NROWS 262144
#define DD 128
#define FEAT 64
#define TILE_M 128
#define NTILES_GRID (NROWS / TILE_M)   // 2048

typedef unsigned long long u64t;

// ---------------------------------------------------------------------------
// Device scratch
// ---------------------------------------------------------------------------
__device__ float g_x0[(size_t)NROWS * DD];
__device__ float g_x1[(size_t)NROWS * DD];

// Weights pre-packed into mma.sync B-fragment lane order, fp16 hi/lo planes.
// Entry e = (kstep*8 + tilepair)*32 + lane  ->  ulonglong2
//   .x = u64{b0,b1} for ntile 2*tp, .y = for ntile 2*tp+1
//   b0 = f16x2(W[k0][n], W[k0+1][n]), b1 = f16x2(W[k0+8][n], W[k0+9][n])
//   k0 = kstep*16 + (lane%4)*2, n = ntile*8 + lane/4
__device__ ulonglong2 g_W1h[4 * 8 * 32];   // K=64  (normalization folded in)
__device__ ulonglong2 g_W1l[4 * 8 * 32];
__device__ ulonglong2 g_W2h[8 * 8 * 32];   // K=128
__device__ ulonglong2 g_W2l[8 * 8 * 32];
__device__ ulonglong2 g_Wnh[8 * 8 * 32];
__device__ ulonglong2 g_Wnl[8 * 8 * 32];
__device__ float g_b1f[DD];                // normalization-folded bias

__device__ __forceinline__ float lk(float x) { return x >= 0.f ? x : 0.01f * x; }

__device__ __forceinline__ uint32_t f2h2(float a, float b) {
    __half2 h = __floats2half2_rn(a, b);
    return *reinterpret_cast<uint32_t*>(&h);
}
__device__ __forceinline__ float2 h22f2(uint32_t u) {
    __half2 h = *reinterpret_cast<__half2*>(&u);
    return __half22float2(h);
}
__device__ __forceinline__ float hiof(float w) {
    return __half2float(__float2half_rn(w));
}
__device__ __forceinline__ u64t pku(uint32_t lo, uint32_t hi) {
    return (u64t)lo | ((u64t)hi << 32);
}

__device__ __forceinline__ uint32_t smem_u32(const void* p) {
    uint32_t a;
    asm("{ .reg .u64 t; cvta.to.shared.u64 t, %1; cvt.u32.u64 %0, t; }" : "=r"(a) : "l"(p));
    return a;
}
__device__ __forceinline__ void ldm4(uint32_t a[4], uint32_t addr) {
    asm volatile("ldmatrix.sync.aligned.m8n8.x4.shared.b16 {%0,%1,%2,%3}, [%4];"
                 : "=r"(a[0]), "=r"(a[1]), "=r"(a[2]), "=r"(a[3]) : "r"(addr));
}
__device__ __forceinline__ void mma16816(float c[4], const uint32_t a[4],
                                         uint32_t b0, uint32_t b1) {
    asm volatile(
        "mma.sync.aligned.m16n8k16.row.col.f32.f16.f16.f32 "
        "{%0,%1,%2,%3},{%4,%5,%6,%7},{%8,%9},{%0,%1,%2,%3};"
        : "+f"(c[0]), "+f"(c[1]), "+f"(c[2]), "+f"(c[3])
        : "r"(a[0]), "r"(a[1]), "r"(a[2]), "r"(a[3]), "r"(b0), "r"(b1));
}

// ---------------------------------------------------------------------------
// Prep: pack weights into B-fragment hi/lo planes; fold normalization into W1/b1.
// block 0 = W1(+b1f), block 1 = W2, block 2 = Wn.
// ---------------------------------------------------------------------------
__global__ void prep(const float* __restrict__ smean, const float* __restrict__ sstd,
                     const float* __restrict__ W1, const float* __restrict__ b1,
                     const float* __restrict__ W2, const float* __restrict__ Wn)
{
    const int tid = threadIdx.x;
    const int bid = blockIdx.x;
    const float* W = (bid == 0) ? W1 : (bid == 1) ? W2 : Wn;
    ulonglong2* dh = (bid == 0) ? g_W1h : (bid == 1) ? g_W2h : g_Wnh;
    ulonglong2* dl = (bid == 0) ? g_W1l : (bid == 1) ? g_W2l : g_Wnl;
    const int nent = (bid == 0) ? 1024 : 2048;

    if (bid == 0) {
        for (int n = tid; n < DD; n += 256) {
            float acc = b1[n];
            for (int k = 0; k < FEAT; k++)
                acc -= smean[k] * (W1[k * DD + n] / (sstd[k] + 0.001f));
            g_b1f[n] = acc;
        }
    }
    for (int e = tid; e < nent; e += 256) {
        int ks = e >> 8, tp = (e >> 5) & 7, l = e & 31;
        u64t H[2], L[2];
        #pragma unroll
        for (int j = 0; j < 2; j++) {
            int n  = (2 * tp + j) * 8 + (l >> 2);
            int k0 = ks * 16 + (l & 3) * 2;
            float w00 = W[(k0    ) * DD + n], w01 = W[(k0 + 1) * DD + n];
            float w08 = W[(k0 + 8) * DD + n], w09 = W[(k0 + 9) * DD + n];
            if (bid == 0) {
                w00 /= (sstd[k0    ] + 0.001f); w01 /= (sstd[k0 + 1] + 0.001f);
                w08 /= (sstd[k0 + 8] + 0.001f); w09 /= (sstd[k0 + 9] + 0.001f);
            }
            H[j] = pku(f2h2(w00, w01), f2h2(w08, w09));
            L[j] = pku(f2h2(w00 - hiof(w00), w01 - hiof(w01)),
                       f2h2(w08 - hiof(w08), w09 - hiof(w09)));
        }
        dh[e] = make_ulonglong2(H[0], H[1]);
        dl[e] = make_ulonglong2(L[0], L[1]);
    }
}

// ---------------------------------------------------------------------------
// Shared HMMA GEMM: C[16 rows x 128 cols] += A[16 x 16*KS] * W, 3-term split.
// A planes at (offAh/offAl), PITCH f16 per row; W fragment planes at offWh/offWl.
// ---------------------------------------------------------------------------
template<int KS, int PITCH>
__device__ __forceinline__ void hgemm(float c[16][4], const char* smem, uint32_t sbase,
                                      int offAh, int offAl, int offWh, int offWl,
                                      int wrow, int lane)
{
    const uint32_t aAh = sbase + offAh + ((wrow + (lane & 15)) * PITCH + (lane >> 4) * 8) * 2;
    const uint32_t aAl = sbase + offAl + ((wrow + (lane & 15)) * PITCH + (lane >> 4) * 8) * 2;
    const ulonglong2* ph = reinterpret_cast<const ulonglong2*>(smem + offWh);
    const ulonglong2* pl = reinterpret_cast<const ulonglong2*>(smem + offWl);
    #pragma unroll
    for (int ks = 0; ks < KS; ks++) {
        uint32_t ah[4], al[4];
        ldm4(ah, aAh + ks * 32);
        ldm4(al, aAl + ks * 32);
        #pragma unroll
        for (int tp = 0; tp < 8; tp++) {
            ulonglong2 wh = ph[(ks * 8 + tp) * 32 + lane];
            ulonglong2 wl = pl[(ks * 8 + tp) * 32 + lane];
            uint32_t h0 = (uint32_t)wh.x, h1 = (uint32_t)(wh.x >> 32);
            uint32_t l0 = (uint32_t)wl.x, l1 = (uint32_t)(wl.x >> 32);
            mma16816(c[2 * tp], ah, h0, h1);
            mma16816(c[2 * tp], ah, l0, l1);
            mma16816(c[2 * tp], al, h0, h1);
            h0 = (uint32_t)wh.y; h1 = (uint32_t)(wh.y >> 32);
            l0 = (uint32_t)wl.y; l1 = (uint32_t)(wl.y >> 32);
            mma16816(c[2 * tp + 1], ah, h0, h1);
            mma16816(c[2 * tp + 1], ah, l0, l1);
            mma16816(c[2 * tp + 1], al, h0, h1);
        }
    }
}

// ---------------------------------------------------------------------------
// Kernel A smem layout (bytes)
// ---------------------------------------------------------------------------
#define A_W1H 0
#define A_W1L 16384
#define A_W2H 32768
#define A_W2L 65536
#define A_AH  98304                 // 128 x 72 f16 = 18432
#define A_AL  (A_AH + 18432)
#define A_HH  (A_AL + 18432)        // 128 x 136 f16 = 34816
#define A_HL  (A_HH + 34816)
#define A_SMEM (A_HL + 34816)       // 204800

__global__ __launch_bounds__(256)
void kernelA(const float* __restrict__ raw, const float* __restrict__ b2)
{
    extern __shared__ char smem[];
    const uint32_t sbase = smem_u32(smem);
    const int tid = threadIdx.x, warp = tid >> 5, lane = tid & 31;
    const int wrow = warp * 16, lane4 = lane & 3, lqr = lane >> 2;
    const int rowbase = blockIdx.x * TILE_M;

    // stage packed weights -> smem (96 KB linear copy)
    {
        uint4* d = reinterpret_cast<uint4*>(smem);
        for (int i = tid; i < 1024; i += 256) d[i] = reinterpret_cast<const uint4*>(g_W1h)[i];
        d = reinterpret_cast<uint4*>(smem + A_W1L);
        for (int i = tid; i < 1024; i += 256) d[i] = reinterpret_cast<const uint4*>(g_W1l)[i];
        d = reinterpret_cast<uint4*>(smem + A_W2H);
        for (int i = tid; i < 2048; i += 256) d[i] = reinterpret_cast<const uint4*>(g_W2h)[i];
        d = reinterpret_cast<uint4*>(smem + A_W2L);
        for (int i = tid; i < 2048; i += 256) d[i] = reinterpret_cast<const uint4*>(g_W2l)[i];
    }
    // stage raw rows as fp16 hi/lo planes (PITCH 72)
    for (int i = 0; i < 16; i++) {
        int row = wrow + i;
        float2 v = reinterpret_cast<const float2*>(raw + (size_t)(rowbase + row) * FEAT)[lane];
        uint32_t hu = f2h2(v.x, v.y);
        float2 hr = h22f2(hu);
        uint32_t lu = f2h2(v.x - hr.x, v.y - hr.y);
        *reinterpret_cast<uint32_t*>(smem + A_AH + (row * 72 + 2 * lane) * 2) = hu;
        *reinterpret_cast<uint32_t*>(smem + A_AL + (row * 72 + 2 * lane) * 2) = lu;
    }
    __syncthreads();

    float c[16][4];
    // ---- GEMM1: h = leaky(x @ W1' + b1') ----
    #pragma unroll
    for (int nt = 0; nt < 16; nt++) {
        float2 b = __ldg(reinterpret_cast<const float2*>(g_b1f + nt * 8 + 2 * lane4));
        c[nt][0] = b.x; c[nt][1] = b.y; c[nt][2] = b.x; c[nt][3] = b.y;
    }
    hgemm<4, 72>(c, smem, sbase, A_AH, A_AL, A_W1H, A_W1L, wrow, lane);

    // h -> fp16 hi/lo planes (PITCH 136); per-warp rows only -> syncwarp
    const int rA = wrow + lqr, rB = rA + 8;
    #pragma unroll
    for (int nt = 0; nt < 16; nt++) {
        int col0 = nt * 8 + 2 * lane4;
        float h0 = lk(c[nt][0]), h1 = lk(c[nt][1]);
        float h2v = lk(c[nt][2]), h3 = lk(c[nt][3]);
        uint32_t hu = f2h2(h0, h1); float2 hr = h22f2(hu);
        *reinterpret_cast<uint32_t*>(smem + A_HH + (rA * 136 + col0) * 2) = hu;
        *reinterpret_cast<uint32_t*>(smem + A_HL + (rA * 136 + col0) * 2) =
            f2h2(h0 - hr.x, h1 - hr.y);
        hu = f2h2(h2v, h3); hr = h22f2(hu);
        *reinterpret_cast<uint32_t*>(smem + A_HH + (rB * 136 + col0) * 2) = hu;
        *reinterpret_cast<uint32_t*>(smem + A_HL + (rB * 136 + col0) * 2) =
            f2h2(h2v - hr.x, h3 - hr.y);
    }
    __syncwarp();

    // ---- GEMM2: y = leaky(leaky(h @ W2 + b2)) + h ----
    #pragma unroll
    for (int nt = 0; nt < 16; nt++) {
        float2 b = __ldg(reinterpret_cast<const float2*>(b2 + nt * 8 + 2 * lane4));
        c[nt][0] = b.x; c[nt][1] = b.y; c[nt][2] = b.x; c[nt][3] = b.y;
    }
    hgemm<8, 136>(c, smem, sbase, A_HH, A_HL, A_W2H, A_W2L, wrow, lane);

    // ---- epilogue: residual + layernorm * 0.5 ----
    float sA = 0.f, qA = 0.f, sB = 0.f, qB = 0.f;
    #pragma unroll
    for (int nt = 0; nt < 16; nt++) {
        int col0 = nt * 8 + 2 * lane4;
        float2 hA = h22f2(*reinterpret_cast<uint32_t*>(smem + A_HH + (rA * 136 + col0) * 2));
        float2 lA = h22f2(*reinterpret_cast<uint32_t*>(smem + A_HL + (rA * 136 + col0) * 2));
        float2 hB = h22f2(*reinterpret_cast<uint32_t*>(smem + A_HH + (rB * 136 + col0) * 2));
        float2 lB = h22f2(*reinterpret_cast<uint32_t*>(smem + A_HL + (rB * 136 + col0) * 2));
        float y0 = lk(lk(c[nt][0])) + (hA.x + lA.x);
        float y1 = lk(lk(c[nt][1])) + (hA.y + lA.y);
        float y2 = lk(lk(c[nt][2])) + (hB.x + lB.x);
        float y3 = lk(lk(c[nt][3])) + (hB.y + lB.y);
        c[nt][0] = y0; c[nt][1] = y1; c[nt][2] = y2; c[nt][3] = y3;
        sA += y0 + y1; qA += y0 * y0 + y1 * y1;
        sB += y2 + y3; qB += y2 * y2 + y3 * y3;
    }
    #pragma unroll
    for (int off = 1; off <= 2; off <<= 1) {
        sA += __shfl_xor_sync(0xffffffffu, sA, off);
        qA += __shfl_xor_sync(0xffffffffu, qA, off);
        sB += __shfl_xor_sync(0xffffffffu, sB, off);
        qB += __shfl_xor_sync(0xffffffffu, qB, off);
    }
    const float invD = 1.f / DD;
    float muA = sA * invD, muB = sB * invD;
    float scA = rsqrtf(qA * invD - muA * muA + 1e-5f) * 0.5f;
    float scB = rsqrtf(qB * invD - muB * muB + 1e-5f) * 0.5f;
    float* dA = g_x0 + (size_t)(rowbase + rA) * DD;
    float* dB = g_x0 + (size_t)(rowbase + rB) * DD;
    #pragma unroll
    for (int nt = 0; nt < 16; nt++) {
        int col0 = nt * 8 + 2 * lane4;
        *reinterpret_cast<float2*>(dA + col0) =
            make_float2((c[nt][0] - muA) * scA, (c[nt][1] - muA) * scA);
        *reinterpret_cast<float2*>(dB + col0) =
            make_float2((c[nt][2] - muB) * scB, (c[nt][3] - muB) * scB);
    }
}

// ---------------------------------------------------------------------------
// Kernel B smem layout
// ---------------------------------------------------------------------------
#define B_WH 0
#define B_WL 32768
#define B_GH 65536                  // 128 x 136 f16
#define B_GL (B_GH + 34816)
#define B_SMEM (B_GL + 34816)       // 135168

template<int PHASE>
__global__ __launch_bounds__(256)
void kernelB(const int* __restrict__ idmap,
             const float* __restrict__ bn, const float* __restrict__ rez,
             const float* __restrict__ Ww, const float* __restrict__ Wv,
             float* __restrict__ outx, float* __restrict__ outw, float* __restrict__ outv)
{
    extern __shared__ char smem[];
    const uint32_t sbase = smem_u32(smem);
    const int tid = threadIdx.x, warp = tid >> 5, lane = tid & 31;
    const int wrow = warp * 16, lane4 = lane & 3, lqr = lane >> 2;
    const int rowbase = blockIdx.x * TILE_M;
    const float* __restrict__ xin = (PHASE == 0) ? g_x0 : g_x1;

    // stage packed Wn -> smem (64 KB)
    {
        uint4* d = reinterpret_cast<uint4*>(smem);
        for (int i = tid; i < 2048; i += 256) d[i] = reinterpret_cast<const uint4*>(g_Wnh)[i];
        d = reinterpret_cast<uint4*>(smem + B_WL);
        for (int i = tid; i < 2048; i += 256) d[i] = reinterpret_cast<const uint4*>(g_Wnl)[i];
    }
    // gather-mean -> fp16 hi/lo planes (coalesced: warp reads full rows)
    for (int i = 0; i < 16; i++) {
        int row = wrow + i;
        int2 pr = __ldg(reinterpret_cast<const int2*>(idmap) + (rowbase + row));
        float4 a = __ldg(reinterpret_cast<const float4*>(xin + (size_t)pr.x * DD) + lane);
        float4 b = __ldg(reinterpret_cast<const float4*>(xin + (size_t)pr.y * DD) + lane);
        float m0 = 0.5f * (a.x + b.x), m1 = 0.5f * (a.y + b.y);
        float m2 = 0.5f * (a.z + b.z), m3 = 0.5f * (a.w + b.w);
        uint32_t h01 = f2h2(m0, m1), h23 = f2h2(m2, m3);
        float2 r01 = h22f2(h01), r23 = h22f2(h23);
        uint32_t l01 = f2h2(m0 - r01.x, m1 - r01.y);
        uint32_t l23 = f2h2(m2 - r23.x, m3 - r23.y);
        *reinterpret_cast<uint2*>(smem + B_GH + (row * 136 + 4 * lane) * 2) = make_uint2(h01, h23);
        *reinterpret_cast<uint2*>(smem + B_GL + (row * 136 + 4 * lane) * 2) = make_uint2(l01, l23);
    }
    __syncthreads();

    float c[16][4];
    #pragma unroll
    for (int nt = 0; nt < 16; nt++) {
        float2 b = __ldg(reinterpret_cast<const float2*>(bn + nt * 8 + 2 * lane4));
        c[nt][0] = b.x; c[nt][1] = b.y; c[nt][2] = b.x; c[nt][3] = b.y;
    }
    hgemm<8, 136>(c, smem, sbase, B_GH, B_GL, B_WH, B_WL, wrow, lane);

    // ---- epilogue: o = xin + leaky(acc) * scale (+ fused w/v GEMV in phase 1)
    const float scale = 0.25f * __ldg(rez);
    const int rA = rowbase + wrow + lqr, rB = rA + 8;
    float* dst = (PHASE == 0) ? g_x1 : outx;
    float pwA = 0.f, pvA = 0.f, pwB = 0.f, pvB = 0.f;
    #pragma unroll
    for (int nt = 0; nt < 16; nt++) {
        int col0 = nt * 8 + 2 * lane4;
        float2 xA = __ldg(reinterpret_cast<const float2*>(xin + (size_t)rA * DD + col0));
        float2 xB = __ldg(reinterpret_cast<const float2*>(xin + (size_t)rB * DD + col0));
        float o0 = xA.x + lk(c[nt][0]) * scale;
        float o1 = xA.y + lk(c[nt][1]) * scale;
        float o2 = xB.x + lk(c[nt][2]) * scale;
        float o3 = xB.y + lk(c[nt][3]) * scale;
        *reinterpret_cast<float2*>(dst + (size_t)rA * DD + col0) = make_float2(o0, o1);
        *reinterpret_cast<float2*>(dst + (size_t)rB * DD + col0) = make_float2(o2, o3);
        if (PHASE == 1) {
            float2 w2 = __ldg(reinterpret_cast<const float2*>(Ww + col0));
            float2 v2 = __ldg(reinterpret_cast<const float2*>(Wv + col0));
            pwA += o0 * w2.x + o1 * w2.y;  pvA += o0 * v2.x + o1 * v2.y;
            pwB += o2 * w2.x + o3 * w2.y;  pvB += o2 * v2.x + o3 * v2.y;
        }
    }
    if (PHASE == 1) {
        #pragma unroll
        for (int off = 1; off <= 2; off <<= 1) {
            pwA += __shfl_xor_sync(0xffffffffu, pwA, off);
            pvA += __shfl_xor_sync(0xffffffffu, pvA, off);
            pwB += __shfl_xor_sync(0xffffffffu, pwB, off);
            pvB += __shfl_xor_sync(0xffffffffu, pvB, off);
        }
        if (lane4 == 0) {
            outw[rA] = pwA; outv[rA] = pvA;
            outw[rB] = pwB; outv[rB] = pvB;
        }
    }
}

// ---------------------------------------------------------------------------
extern "C" void kernel_launch(void* const* d_in, const int* in_sizes, int n_in,
                              void* d_out, int out_size)
{
    const float* raw   = (const float*)d_in[0];
    // d_in[1] = uids (unused)
    const int*   idmap = (const int*)  d_in[2];
    const float* smean = (const float*)d_in[3];
    const float* sstd  = (const float*)d_in[4];
    const float* W1    = (const float*)d_in[5];
    const float* b1    = (const float*)d_in[6];
    const float* W2    = (const float*)d_in[7];
    const float* b2    = (const float*)d_in[8];
    const float* Wn    = (const float*)d_in[9];
    const float* bn    = (const float*)d_in[10];
    const float* rez   = (const float*)d_in[11];
    const float* Ww    = (const float*)d_in[12];
    const float* Wv    = (const float*)d_in[13];
    float* out = (float*)d_out;

    cudaFuncSetAttribute(kernelA,    cudaFuncAttributeMaxDynamicSharedMemorySize, A_SMEM);
    cudaFuncSetAttribute(kernelB<0>, cudaFuncAttributeMaxDynamicSharedMemorySize, B_SMEM);
    cudaFuncSetAttribute(kernelB<1>, cudaFuncAttributeMaxDynamicSharedMemorySize, B_SMEM);

    prep<<<3, 256>>>(smean, sstd, W1, b1, W2, Wn);
    kernelA<<<NTILES_GRID, 256, A_SMEM>>>(raw, b2);
    kernelB<0><<<NTILES_GRID, 256, B_SMEM>>>(idmap, bn, rez, Ww, Wv,
                                             nullptr, nullptr, nullptr);
    kernelB<1><<<NTILES_GRID, 256, B_SMEM>>>(idmap, bn, rez, Ww, Wv,
                                             out,
                                             out + (size_t)NROWS * DD,
                                             out + (size_t)NROWS * DD + NROWS);
}

// round 9
// speedup vs baseline: 1.6420x; 1.2610x over previous
#include <cuda_runtime.h>
#include <cuda_fp16.h>
#include <cstdint>

#define NROWS 262144
#define DD 128
#define FEAT 64
#define TILE_M 256
#define NTILES_GRID (NROWS / TILE_M)   // 1024
#define NTHREADS 512

typedef unsigned long long u64t;

// ---------------------------------------------------------------------------
// Device scratch
// ---------------------------------------------------------------------------
__device__ float g_x0[(size_t)NROWS * DD];
__device__ float g_x1[(size_t)NROWS * DD];

// Weights pre-packed into mma.sync B-fragment lane order, fp16 hi/lo planes.
// Entry e = (kstep*8 + tilepair)*32 + lane  ->  ulonglong2
//   .x = u64{b0,b1} for ntile 2*tp, .y = for ntile 2*tp+1
//   b0 = f16x2(W[k0][n], W[k0+1][n]), b1 = f16x2(W[k0+8][n], W[k0+9][n])
//   k0 = kstep*16 + (lane%4)*2, n = ntile*8 + lane/4
__device__ ulonglong2 g_W1h[4 * 8 * 32];   // K=64  (normalization folded in)
__device__ ulonglong2 g_W1l[4 * 8 * 32];
__device__ ulonglong2 g_W2h[8 * 8 * 32];   // K=128
__device__ ulonglong2 g_W2l[8 * 8 * 32];
__device__ ulonglong2 g_Wnh[8 * 8 * 32];
__device__ ulonglong2 g_Wnl[8 * 8 * 32];
__device__ float g_b1f[DD];                // normalization-folded bias

__device__ __forceinline__ float lk(float x) { return x >= 0.f ? x : 0.01f * x; }

__device__ __forceinline__ uint32_t f2h2(float a, float b) {
    __half2 h = __floats2half2_rn(a, b);
    return *reinterpret_cast<uint32_t*>(&h);
}
__device__ __forceinline__ float2 h22f2(uint32_t u) {
    __half2 h = *reinterpret_cast<__half2*>(&u);
    return __half22float2(h);
}
__device__ __forceinline__ float hiof(float w) {
    return __half2float(__float2half_rn(w));
}
__device__ __forceinline__ u64t pku(uint32_t lo, uint32_t hi) {
    return (u64t)lo | ((u64t)hi << 32);
}

__device__ __forceinline__ uint32_t smem_u32(const void* p) {
    uint32_t a;
    asm("{ .reg .u64 t; cvta.to.shared.u64 t, %1; cvt.u32.u64 %0, t; }" : "=r"(a) : "l"(p));
    return a;
}
__device__ __forceinline__ void ldm4(uint32_t a[4], uint32_t addr) {
    asm volatile("ldmatrix.sync.aligned.m8n8.x4.shared.b16 {%0,%1,%2,%3}, [%4];"
                 : "=r"(a[0]), "=r"(a[1]), "=r"(a[2]), "=r"(a[3]) : "r"(addr));
}
__device__ __forceinline__ void mma16816(float c[4], const uint32_t a[4],
                                         uint32_t b0, uint32_t b1) {
    asm volatile(
        "mma.sync.aligned.m16n8k16.row.col.f32.f16.f16.f32 "
        "{%0,%1,%2,%3},{%4,%5,%6,%7},{%8,%9},{%0,%1,%2,%3};"
        : "+f"(c[0]), "+f"(c[1]), "+f"(c[2]), "+f"(c[3])
        : "r"(a[0]), "r"(a[1]), "r"(a[2]), "r"(a[3]), "r"(b0), "r"(b1));
}

// ---------------------------------------------------------------------------
// Prep: pack weights into B-fragment hi/lo planes; fold normalization into W1/b1.
// block 0 = W1(+b1f), block 1 = W2, block 2 = Wn.
// ---------------------------------------------------------------------------
__global__ void prep(const float* __restrict__ smean, const float* __restrict__ sstd,
                     const float* __restrict__ W1, const float* __restrict__ b1,
                     const float* __restrict__ W2, const float* __restrict__ Wn)
{
    const int tid = threadIdx.x;
    const int bid = blockIdx.x;
    const float* W = (bid == 0) ? W1 : (bid == 1) ? W2 : Wn;
    ulonglong2* dh = (bid == 0) ? g_W1h : (bid == 1) ? g_W2h : g_Wnh;
    ulonglong2* dl = (bid == 0) ? g_W1l : (bid == 1) ? g_W2l : g_Wnl;
    const int nent = (bid == 0) ? 1024 : 2048;

    if (bid == 0) {
        for (int n = tid; n < DD; n += 256) {
            float acc = b1[n];
            for (int k = 0; k < FEAT; k++)
                acc -= smean[k] * (W1[k * DD + n] / (sstd[k] + 0.001f));
            g_b1f[n] = acc;
        }
    }
    for (int e = tid; e < nent; e += 256) {
        int ks = e >> 8, tp = (e >> 5) & 7, l = e & 31;
        u64t H[2], L[2];
        #pragma unroll
        for (int j = 0; j < 2; j++) {
            int n  = (2 * tp + j) * 8 + (l >> 2);
            int k0 = ks * 16 + (l & 3) * 2;
            float w00 = W[(k0    ) * DD + n], w01 = W[(k0 + 1) * DD + n];
            float w08 = W[(k0 + 8) * DD + n], w09 = W[(k0 + 9) * DD + n];
            if (bid == 0) {
                w00 /= (sstd[k0    ] + 0.001f); w01 /= (sstd[k0 + 1] + 0.001f);
                w08 /= (sstd[k0 + 8] + 0.001f); w09 /= (sstd[k0 + 9] + 0.001f);
            }
            H[j] = pku(f2h2(w00, w01), f2h2(w08, w09));
            L[j] = pku(f2h2(w00 - hiof(w00), w01 - hiof(w01)),
                       f2h2(w08 - hiof(w08), w09 - hiof(w09)));
        }
        dh[e] = make_ulonglong2(H[0], H[1]);
        dl[e] = make_ulonglong2(L[0], L[1]);
    }
}

// ---------------------------------------------------------------------------
// Shared HMMA GEMM: C[16 rows x 128 cols] += A[16 x 16*KS] * W, 3-term split.
// A planes at (offAh/offAl), PITCH f16 per row; W fragment planes at offWh/offWl.
// ---------------------------------------------------------------------------
template<int KS, int PITCH>
__device__ __forceinline__ void hgemm(float c[16][4], const char* smem, uint32_t sbase,
                                      int offAh, int offAl, int offWh, int offWl,
                                      int wrow, int lane)
{
    const uint32_t aAh = sbase + offAh + ((wrow + (lane & 15)) * PITCH + (lane >> 4) * 8) * 2;
    const uint32_t aAl = sbase + offAl + ((wrow + (lane & 15)) * PITCH + (lane >> 4) * 8) * 2;
    const ulonglong2* ph = reinterpret_cast<const ulonglong2*>(smem + offWh);
    const ulonglong2* pl = reinterpret_cast<const ulonglong2*>(smem + offWl);
    #pragma unroll
    for (int ks = 0; ks < KS; ks++) {
        uint32_t ah[4], al[4];
        ldm4(ah, aAh + ks * 32);
        ldm4(al, aAl + ks * 32);
        #pragma unroll
        for (int tp = 0; tp < 8; tp++) {
            ulonglong2 wh = ph[(ks * 8 + tp) * 32 + lane];
            ulonglong2 wl = pl[(ks * 8 + tp) * 32 + lane];
            uint32_t h0 = (uint32_t)wh.x, h1 = (uint32_t)(wh.x >> 32);
            uint32_t l0 = (uint32_t)wl.x, l1 = (uint32_t)(wl.x >> 32);
            mma16816(c[2 * tp], ah, h0, h1);
            mma16816(c[2 * tp], ah, l0, l1);
            mma16816(c[2 * tp], al, h0, h1);
            h0 = (uint32_t)wh.y; h1 = (uint32_t)(wh.y >> 32);
            l0 = (uint32_t)wl.y; l1 = (uint32_t)(wl.y >> 32);
            mma16816(c[2 * tp + 1], ah, h0, h1);
            mma16816(c[2 * tp + 1], ah, l0, l1);
            mma16816(c[2 * tp + 1], al, h0, h1);
        }
    }
}

// ---------------------------------------------------------------------------
// Kernel A smem layout (bytes). TILE_M=256, 512 threads, 16 warps.
// W2 planes resident; {W1 planes + A planes} union-overlaid by H planes.
// ---------------------------------------------------------------------------
#define A_W2H 0                      // 32 KB
#define A_W2L 32768                  // 32 KB
#define A_W1H 65536                  // 16 KB   (phase 1)
#define A_W1L 81920                  // 16 KB   (phase 1)
#define A_AH  98304                  // 256 x 72 f16 = 36864 (phase 1)
#define A_AL  135168                 // 36864 (phase 1)
#define A_HH  65536                  // 256 x 136 f16 = 69632 (phase 2; == W1H+W1L+AH)
#define A_HL  135168                 // 69632 (phase 2)
#define A_SMEM 204800                // 200 KB

__global__ __launch_bounds__(NTHREADS)
void kernelA(const float* __restrict__ raw, const float* __restrict__ b2)
{
    extern __shared__ char smem[];
    const uint32_t sbase = smem_u32(smem);
    const int tid = threadIdx.x, warp = tid >> 5, lane = tid & 31;
    const int wrow = warp * 16, lane4 = lane & 3, lqr = lane >> 2;
    const int rowbase = blockIdx.x * TILE_M;

    // stage packed weights -> smem (96 KB linear copy)
    {
        uint4* d = reinterpret_cast<uint4*>(smem + A_W2H);
        for (int i = tid; i < 2048; i += NTHREADS) d[i] = reinterpret_cast<const uint4*>(g_W2h)[i];
        d = reinterpret_cast<uint4*>(smem + A_W2L);
        for (int i = tid; i < 2048; i += NTHREADS) d[i] = reinterpret_cast<const uint4*>(g_W2l)[i];
        d = reinterpret_cast<uint4*>(smem + A_W1H);
        for (int i = tid; i < 1024; i += NTHREADS) d[i] = reinterpret_cast<const uint4*>(g_W1h)[i];
        d = reinterpret_cast<uint4*>(smem + A_W1L);
        for (int i = tid; i < 1024; i += NTHREADS) d[i] = reinterpret_cast<const uint4*>(g_W1l)[i];
    }
    // stage raw rows as fp16 hi/lo planes (PITCH 72)
    #pragma unroll 4
    for (int i = 0; i < 16; i++) {
        int row = wrow + i;
        float2 v = __ldg(reinterpret_cast<const float2*>(raw + (size_t)(rowbase + row) * FEAT) + lane);
        uint32_t hu = f2h2(v.x, v.y);
        float2 hr = h22f2(hu);
        uint32_t lu = f2h2(v.x - hr.x, v.y - hr.y);
        *reinterpret_cast<uint32_t*>(smem + A_AH + (row * 72 + 2 * lane) * 2) = hu;
        *reinterpret_cast<uint32_t*>(smem + A_AL + (row * 72 + 2 * lane) * 2) = lu;
    }
    __syncthreads();

    float c[16][4];
    // ---- GEMM1: h = leaky(x @ W1' + b1') ----
    #pragma unroll
    for (int nt = 0; nt < 16; nt++) {
        float2 b = __ldg(reinterpret_cast<const float2*>(g_b1f + nt * 8 + 2 * lane4));
        c[nt][0] = b.x; c[nt][1] = b.y; c[nt][2] = b.x; c[nt][3] = b.y;
    }
    hgemm<4, 72>(c, smem, sbase, A_AH, A_AL, A_W1H, A_W1L, wrow, lane);

    // all warps done with W1/A before H overwrites that region
    __syncthreads();

    // h -> fp16 hi/lo planes (PITCH 136)
    const int rA = wrow + lqr, rB = rA + 8;
    #pragma unroll
    for (int nt = 0; nt < 16; nt++) {
        int col0 = nt * 8 + 2 * lane4;
        float h0 = lk(c[nt][0]), h1 = lk(c[nt][1]);
        float h2v = lk(c[nt][2]), h3 = lk(c[nt][3]);
        uint32_t hu = f2h2(h0, h1); float2 hr = h22f2(hu);
        *reinterpret_cast<uint32_t*>(smem + A_HH + (rA * 136 + col0) * 2) = hu;
        *reinterpret_cast<uint32_t*>(smem + A_HL + (rA * 136 + col0) * 2) =
            f2h2(h0 - hr.x, h1 - hr.y);
        hu = f2h2(h2v, h3); hr = h22f2(hu);
        *reinterpret_cast<uint32_t*>(smem + A_HH + (rB * 136 + col0) * 2) = hu;
        *reinterpret_cast<uint32_t*>(smem + A_HL + (rB * 136 + col0) * 2) =
            f2h2(h2v - hr.x, h3 - hr.y);
    }
    __syncthreads();

    // ---- GEMM2: y = leaky(leaky(h @ W2 + b2)) + h ----
    #pragma unroll
    for (int nt = 0; nt < 16; nt++) {
        float2 b = __ldg(reinterpret_cast<const float2*>(b2 + nt * 8 + 2 * lane4));
        c[nt][0] = b.x; c[nt][1] = b.y; c[nt][2] = b.x; c[nt][3] = b.y;
    }
    hgemm<8, 136>(c, smem, sbase, A_HH, A_HL, A_W2H, A_W2L, wrow, lane);

    // ---- epilogue: residual + layernorm * 0.5 ----
    float sA = 0.f, qA = 0.f, sB = 0.f, qB = 0.f;
    #pragma unroll
    for (int nt = 0; nt < 16; nt++) {
        int col0 = nt * 8 + 2 * lane4;
        float2 hA = h22f2(*reinterpret_cast<uint32_t*>(smem + A_HH + (rA * 136 + col0) * 2));
        float2 lA = h22f2(*reinterpret_cast<uint32_t*>(smem + A_HL + (rA * 136 + col0) * 2));
        float2 hB = h22f2(*reinterpret_cast<uint32_t*>(smem + A_HH + (rB * 136 + col0) * 2));
        float2 lB = h22f2(*reinterpret_cast<uint32_t*>(smem + A_HL + (rB * 136 + col0) * 2));
        float y0 = lk(lk(c[nt][0])) + (hA.x + lA.x);
        float y1 = lk(lk(c[nt][1])) + (hA.y + lA.y);
        float y2 = lk(lk(c[nt][2])) + (hB.x + lB.x);
        float y3 = lk(lk(c[nt][3])) + (hB.y + lB.y);
        c[nt][0] = y0; c[nt][1] = y1; c[nt][2] = y2; c[nt][3] = y3;
        sA += y0 + y1; qA += y0 * y0 + y1 * y1;
        sB += y2 + y3; qB += y2 * y2 + y3 * y3;
    }
    #pragma unroll
    for (int off = 1; off <= 2; off <<= 1) {
        sA += __shfl_xor_sync(0xffffffffu, sA, off);
        qA += __shfl_xor_sync(0xffffffffu, qA, off);
        sB += __shfl_xor_sync(0xffffffffu, sB, off);
        qB += __shfl_xor_sync(0xffffffffu, qB, off);
    }
    const float invD = 1.f / DD;
    float muA = sA * invD, muB = sB * invD;
    float scA = rsqrtf(qA * invD - muA * muA + 1e-5f) * 0.5f;
    float scB = rsqrtf(qB * invD - muB * muB + 1e-5f) * 0.5f;
    float* dA = g_x0 + (size_t)(rowbase + rA) * DD;
    float* dB = g_x0 + (size_t)(rowbase + rB) * DD;
    #pragma unroll
    for (int nt = 0; nt < 16; nt++) {
        int col0 = nt * 8 + 2 * lane4;
        *reinterpret_cast<float2*>(dA + col0) =
            make_float2((c[nt][0] - muA) * scA, (c[nt][1] - muA) * scA);
        *reinterpret_cast<float2*>(dB + col0) =
            make_float2((c[nt][2] - muB) * scB, (c[nt][3] - muB) * scB);
    }
}

// ---------------------------------------------------------------------------
// Kernel B smem layout. TILE_M=256, 512 threads.
// ---------------------------------------------------------------------------
#define B_WH 0                       // 32 KB
#define B_WL 32768                   // 32 KB
#define B_GH 65536                   // 256 x 136 f16 = 69632
#define B_GL (B_GH + 69632)
#define B_SMEM (B_GL + 69632)        // 204800

template<int PHASE>
__global__ __launch_bounds__(NTHREADS)
void kernelB(const int* __restrict__ idmap,
             const float* __restrict__ bn, const float* __restrict__ rez,
             const float* __restrict__ Ww, const float* __restrict__ Wv,
             float* __restrict__ outx, float* __restrict__ outw, float* __restrict__ outv)
{
    extern __shared__ char smem[];
    const uint32_t sbase = smem_u32(smem);
    const int tid = threadIdx.x, warp = tid >> 5, lane = tid & 31;
    const int wrow = warp * 16, lane4 = lane & 3, lqr = lane >> 2;
    const int rowbase = blockIdx.x * TILE_M;
    const float* __restrict__ xin = (PHASE == 0) ? g_x0 : g_x1;

    // stage packed Wn -> smem (64 KB)
    {
        uint4* d = reinterpret_cast<uint4*>(smem + B_WH);
        for (int i = tid; i < 2048; i += NTHREADS) d[i] = reinterpret_cast<const uint4*>(g_Wnh)[i];
        d = reinterpret_cast<uint4*>(smem + B_WL);
        for (int i = tid; i < 2048; i += NTHREADS) d[i] = reinterpret_cast<const uint4*>(g_Wnl)[i];
    }
    // gather-mean -> fp16 hi/lo planes (coalesced: warp reads full rows)
    #pragma unroll 4
    for (int i = 0; i < 16; i++) {
        int row = wrow + i;
        int2 pr = __ldg(reinterpret_cast<const int2*>(idmap) + (rowbase + row));
        float4 a = __ldg(reinterpret_cast<const float4*>(xin + (size_t)pr.x * DD) + lane);
        float4 b = __ldg(reinterpret_cast<const float4*>(xin + (size_t)pr.y * DD) + lane);
        float m0 = 0.5f * (a.x + b.x), m1 = 0.5f * (a.y + b.y);
        float m2 = 0.5f * (a.z + b.z), m3 = 0.5f * (a.w + b.w);
        uint32_t h01 = f2h2(m0, m1), h23 = f2h2(m2, m3);
        float2 r01 = h22f2(h01), r23 = h22f2(h23);
        uint32_t l01 = f2h2(m0 - r01.x, m1 - r01.y);
        uint32_t l23 = f2h2(m2 - r23.x, m3 - r23.y);
        *reinterpret_cast<uint2*>(smem + B_GH + (row * 136 + 4 * lane) * 2) = make_uint2(h01, h23);
        *reinterpret_cast<uint2*>(smem + B_GL + (row * 136 + 4 * lane) * 2) = make_uint2(l01, l23);
    }
    __syncthreads();

    float c[16][4];
    #pragma unroll
    for (int nt = 0; nt < 16; nt++) {
        float2 b = __ldg(reinterpret_cast<const float2*>(bn + nt * 8 + 2 * lane4));
        c[nt][0] = b.x; c[nt][1] = b.y; c[nt][2] = b.x; c[nt][3] = b.y;
    }
    hgemm<8, 136>(c, smem, sbase, B_GH, B_GL, B_WH, B_WL, wrow, lane);

    // ---- epilogue: o = xin + leaky(acc) * scale (+ fused w/v GEMV in phase 1)
    const float scale = 0.25f * __ldg(rez);
    const int rA = rowbase + wrow + lqr, rB = rA + 8;
    float* dst = (PHASE == 0) ? g_x1 : outx;
    float pwA = 0.f, pvA = 0.f, pwB = 0.f, pvB = 0.f;
    #pragma unroll
    for (int nt = 0; nt < 16; nt++) {
        int col0 = nt * 8 + 2 * lane4;
        float2 xA = __ldg(reinterpret_cast<const float2*>(xin + (size_t)rA * DD + col0));
        float2 xB = __ldg(reinterpret_cast<const float2*>(xin + (size_t)rB * DD + col0));
        float o0 = xA.x + lk(c[nt][0]) * scale;
        float o1 = xA.y + lk(c[nt][1]) * scale;
        float o2 = xB.x + lk(c[nt][2]) * scale;
        float o3 = xB.y + lk(c[nt][3]) * scale;
        *reinterpret_cast<float2*>(dst + (size_t)rA * DD + col0) = make_float2(o0, o1);
        *reinterpret_cast<float2*>(dst + (size_t)rB * DD + col0) = make_float2(o2, o3);
        if (PHASE == 1) {
            float2 w2 = __ldg(reinterpret_cast<const float2*>(Ww + col0));
            float2 v2 = __ldg(reinterpret_cast<const float2*>(Wv + col0));
            pwA += o0 * w2.x + o1 * w2.y;  pvA += o0 * v2.x + o1 * v2.y;
            pwB += o2 * w2.x + o3 * w2.y;  pvB += o2 * v2.x + o3 * v2.y;
        }
    }
    if (PHASE == 1) {
        #pragma unroll
        for (int off = 1; off <= 2; off <<= 1) {
            pwA += __shfl_xor_sync(0xffffffffu, pwA, off);
            pvA += __shfl_xor_sync(0xffffffffu, pvA, off);
            pwB += __shfl_xor_sync(0xffffffffu, pwB, off);
            pvB += __shfl_xor_sync(0xffffffffu, pvB, off);
        }
        if (lane4 == 0) {
            outw[rA] = pwA; outv[rA] = pvA;
            outw[rB] = pwB; outv[rB] = pvB;
        }
    }
}

// ---------------------------------------------------------------------------
extern "C" void kernel_launch(void* const* d_in, const int* in_sizes, int n_in,
                              void* d_out, int out_size)
{
    const float* raw   = (const float*)d_in[0];
    // d_in[1] = uids (unused)
    const int*   idmap = (const int*)  d_in[2];
    const float* smean = (const float*)d_in[3];
    const float* sstd  = (const float*)d_in[4];
    const float* W1    = (const float*)d_in[5];
    const float* b1    = (const float*)d_in[6];
    const float* W2    = (const float*)d_in[7];
    const float* b2    = (const float*)d_in[8];
    const float* Wn    = (const float*)d_in[9];
    const float* bn    = (const float*)d_in[10];
    const float* rez   = (const float*)d_in[11];
    const float* Ww    = (const float*)d_in[12];
    const float* Wv    = (const float*)d_in[13];
    float* out = (float*)d_out;

    cudaFuncSetAttribute(kernelA,    cudaFuncAttributeMaxDynamicSharedMemorySize, A_SMEM);
    cudaFuncSetAttribute(kernelB<0>, cudaFuncAttributeMaxDynamicSharedMemorySize, B_SMEM);
    cudaFuncSetAttribute(kernelB<1>, cudaFuncAttributeMaxDynamicSharedMemorySize, B_SMEM);

    prep<<<3, 256>>>(smean, sstd, W1, b1, W2, Wn);
    kernelA<<<NTILES_GRID, NTHREADS, A_SMEM>>>(raw, b2);
    kernelB<0><<<NTILES_GRID, NTHREADS, B_SMEM>>>(idmap, bn, rez, Ww, Wv,
                                                  nullptr, nullptr, nullptr);
    kernelB<1><<<NTILES_GRID, NTHREADS, B_SMEM>>>(idmap, bn, rez, Ww, Wv,
                                                  out,
                                                  out + (size_t)NROWS * DD,
                                                  out + (size_t)NROWS * DD + NROWS);
}